// round 6
// baseline (speedup 1.0000x reference)
#include <cuda_runtime.h>
#include <cstdint>

// ---------------------------------------------------------------------------
// PoincareInputBlock: projx -> logmap0 -> conv3x3+bias -> exp/proj/log ->
// BN(batch stats) -> exp/proj/log -> relu -> expmap0+projx
// x:[16,3,224,224] f32, w:[3,3,3,64] HWIO, out:[16,224,224,64] f32
// ---------------------------------------------------------------------------

#define B_ 16
#define H_ 224
#define W_ 224
#define CIN 3
#define COUT 64
#define HWSZ (H_*W_)
#define NPIX (B_*H_*W_)          // 802816
#define TW 32                    // tile width (pixels)
#define TH 4                     // tile height
#define NBX (W_/TW)              // 7
#define NBY (H_/TH)              // 56
#define NBLK (NBX*NBY*B_)        // 6272

typedef unsigned long long u64;

// scratch (device globals are the sanctioned scratch mechanism)
__device__ float g_tlog[NPIX*CIN];          // tangent-space input, NHWC, 9.6MB
__device__ float g_partials[128*NBLK];      // per-block sums(64) + sumsq(64)
__device__ float g_scale[COUT];
__device__ float g_shift[COUT];

// ---------------- packed f32x2 helpers -------------------------------------
__device__ __forceinline__ u64 pk(float a, float b) {
    u64 r;
    asm("mov.b64 %0, {%1, %2};" : "=l"(r)
        : "r"(__float_as_uint(a)), "r"(__float_as_uint(b)));
    return r;
}
__device__ __forceinline__ u64 pk2(float a) { return pk(a, a); }
__device__ __forceinline__ void upk(u64 v, float& a, float& b) {
    unsigned lo, hi;
    asm("mov.b64 {%0, %1}, %2;" : "=r"(lo), "=r"(hi) : "l"(v));
    a = __uint_as_float(lo); b = __uint_as_float(hi);
}
__device__ __forceinline__ u64 pfma(u64 a, u64 b, u64 c) {
    u64 d;
    asm("fma.rn.f32x2 %0, %1, %2, %3;" : "=l"(d) : "l"(a), "l"(b), "l"(c));
    return d;
}
__device__ __forceinline__ u64 pmul(u64 a, u64 b) {
    u64 d;
    asm("mul.rn.f32x2 %0, %1, %2;" : "=l"(d) : "l"(a), "l"(b));
    return d;
}
__device__ __forceinline__ u64 padd(u64 a, u64 b) {
    u64 d;
    asm("add.rn.f32x2 %0, %1, %2;" : "=l"(d) : "l"(a), "l"(b));
    return d;
}

// ---------------- robust scalar math (fast-math-proof) ----------------------
__device__ __forceinline__ float my_tanh(float n) {   // n >= 0
    if (n < 0.1f) {
        float n2 = n * n;
        return n * (1.0f + n2 * (-0.33333334f + n2 * 0.13333334f));
    }
    float E = expf(2.0f * n);            // overflow -> inf -> t = 1 (correct)
    return 1.0f - 2.0f / (E + 1.0f);
}
__device__ __forceinline__ float my_atanh(float t) {  // 0 <= t < 1
    if (t < 0.1f) {
        float t2 = t * t;
        return t * (1.0f + t2 * (0.33333334f + t2 * (0.2f + t2 * 0.14285715f)));
    }
    return 0.5f * logf((1.0f + t) / (1.0f - t));      // 1-t exact (Sterbenz)
}

// scale factor of logmap0(projx(expmap0(v))) given ||v||^2
__device__ __forceinline__ float chain_log_exp(float nsq) {
    float nu = sqrtf(nsq);
    float n1 = fmaxf(nu, 1e-7f);
    float th = my_tanh(n1);
    float se = th / n1;                  // expmap0 scale
    float hp = se * nu;                  // ||h_pre||
    float n2 = fmaxf(hp, 1e-7f);
    float sp = fminf(1.0f, 0.999f / n2); // projx scale
    float hn = hp * sp;
    float n3 = fmaxf(hn, 1e-7f);
    float tt = fminf(n3, 0.99999f);
    float sl = my_atanh(tt) / n3;        // logmap0 scale
    return sl * sp * se;
}
// scale factor of projx(expmap0(v)) given ||v||^2
__device__ __forceinline__ float chain_exp(float nsq) {
    float nu = sqrtf(nsq);
    float n1 = fmaxf(nu, 1e-7f);
    float th = my_tanh(n1);
    float se = th / n1;
    float hp = se * nu;
    float n2 = fmaxf(hp, 1e-7f);
    float sp = fminf(1.0f, 0.999f / n2);
    return se * sp;
}

// ---------------- K0: tangent-space input  (NCHW -> NHWC tlog) --------------
__global__ void k0_tlog(const float* __restrict__ x) {
    int idx = blockIdx.x * 256 + threadIdx.x;        // exactly NPIX threads
    int b   = idx / HWSZ;
    int hw  = idx - b * HWSZ;
    const float* xb = x + b * (CIN * HWSZ);
    float x0 = xb[hw], x1 = xb[HWSZ + hw], x2 = xb[2 * HWSZ + hw];
    float nsq = x0 * x0 + x1 * x1 + x2 * x2;
    float nu = sqrtf(nsq);
    float n1 = fmaxf(nu, 1e-7f);
    float sp = fminf(1.0f, 0.999f / n1);             // projx
    float hn = nu * sp;
    float n3 = fmaxf(hn, 1e-7f);
    float tt = fminf(n3, 0.99999f);
    float g  = sp * my_atanh(tt) / n3;               // logmap0
    float* o = g_tlog + (size_t)idx * 3;
    o[0] = g * x0; o[1] = g * x1; o[2] = g * x2;
}

// ---------------- shared conv core ------------------------------------------
// Each thread = one pixel; acc[i] holds packed channels (2i, 2i+1).
__device__ __forceinline__ void conv_pixel(const float* st, const float* sw,
                                           const float* sb, int ty, int tx,
                                           u64 acc[32]) {
#pragma unroll
    for (int i = 0; i < 32; ++i)
        acc[i] = *(const u64*)(sb + 2 * i);
#pragma unroll
    for (int dy = 0; dy < 3; ++dy)
#pragma unroll
        for (int dx = 0; dx < 3; ++dx)
#pragma unroll
            for (int ci = 0; ci < 3; ++ci) {
                float tv = st[(ty + dy) * 102 + (tx + dx) * 3 + ci];
                u64 tv2 = pk2(tv);
                const u64* wr = (const u64*)(sw + ((dy * 3 + dx) * 3 + ci) * 64);
#pragma unroll
                for (int i = 0; i < 32; ++i)
                    acc[i] = pfma(tv2, wr[i], acc[i]);
            }
}

__device__ __forceinline__ void load_tile_and_weights(
        const float* __restrict__ cw, const float* __restrict__ cb,
        float* sw, float* sb, float* st, int tid) {
    for (int i = tid; i < 1728; i += 128) sw[i] = cw[i];
    if (tid < 64) sb[tid] = cb[tid];
    int w0 = blockIdx.x * TW, h0 = blockIdx.y * TH, b = blockIdx.z;
    for (int i = tid; i < 6 * 102; i += 128) {
        int r  = i / 102;
        int k  = i - r * 102;
        int c3 = k / 3;
        int ci = k - c3 * 3;
        int gh = h0 - 1 + r;
        int gw = w0 - 1 + c3;
        float v = 0.0f;
        if ((unsigned)gh < (unsigned)H_ && (unsigned)gw < (unsigned)W_)
            v = g_tlog[((size_t)(b * H_ + gh) * W_ + gw) * 3 + ci];
        st[i] = v;
    }
}

// ---------------- K1: conv + f1 -> per-block channel stats ------------------
__global__ void __launch_bounds__(128, 4)
k1_stats(const float* __restrict__ cw, const float* __restrict__ cb) {
    __shared__ __align__(16) float sw[1728];
    __shared__ __align__(16) float sb[COUT];
    __shared__ float st[6 * 102];
    __shared__ u64 u2buf[TH][32][33];     // padded to kill bank conflicts
    __shared__ u64 wpart[TH][32][2];

    int tx = threadIdx.x, ty = threadIdx.y;
    int tid = ty * 32 + tx;
    load_tile_and_weights(cw, cb, sw, sb, st, tid);
    __syncthreads();

    u64 acc[32];
    conv_pixel(st, sw, sb, ty, tx, acc);

    u64 q2 = 0ull;
#pragma unroll
    for (int i = 0; i < 32; ++i) q2 = pfma(acc[i], acc[i], q2);
    float qa, qb; upk(q2, qa, qb);
    float f1 = chain_log_exp(qa + qb);
    u64 f1p = pk2(f1);
#pragma unroll
    for (int i = 0; i < 32; ++i) acc[i] = pmul(acc[i], f1p);   // u2 = f1*u

    // warp-local transpose via smem: lane -> channel pair
#pragma unroll
    for (int i = 0; i < 32; ++i) u2buf[ty][tx][i] = acc[i];
    __syncwarp();
    u64 s = 0ull, q = 0ull;
#pragma unroll
    for (int p = 0; p < 32; ++p) {
        u64 v = u2buf[ty][p][tx];
        s = padd(s, v);
        q = pfma(v, v, q);
    }
    wpart[ty][tx][0] = s;
    wpart[ty][tx][1] = q;
    __syncthreads();
    if (ty == 0) {
        u64 S = 0ull, Q = 0ull;
#pragma unroll
        for (int w = 0; w < TH; ++w) {
            S = padd(S, wpart[w][tx][0]);
            Q = padd(Q, wpart[w][tx][1]);
        }
        float s0, s1, q0, q1;
        upk(S, s0, s1); upk(Q, q0, q1);
        int blk = (blockIdx.z * NBY + blockIdx.y) * NBX + blockIdx.x;
        g_partials[(2 * tx) * NBLK + blk]          = s0;
        g_partials[(2 * tx + 1) * NBLK + blk]      = s1;
        g_partials[(64 + 2 * tx) * NBLK + blk]     = q0;
        g_partials[(64 + 2 * tx + 1) * NBLK + blk] = q1;
    }
}

// ---------------- K2: finalize BN scale/shift (deterministic) ---------------
__global__ void k2_finalize(const float* __restrict__ gamma,
                            const float* __restrict__ beta) {
    int c = blockIdx.x, tid = threadIdx.x;
    const float* ps = g_partials + (size_t)c * NBLK;
    const float* pq = g_partials + (size_t)(64 + c) * NBLK;
    float s = 0.0f, q = 0.0f;
    for (int i = tid; i < NBLK; i += 256) { s += ps[i]; q += pq[i]; }
    __shared__ float rs[256], rq[256];
    rs[tid] = s; rq[tid] = q;
    __syncthreads();
    for (int stp = 128; stp > 0; stp >>= 1) {
        if (tid < stp) { rs[tid] += rs[tid + stp]; rq[tid] += rq[tid + stp]; }
        __syncthreads();
    }
    if (tid == 0) {
        float inv  = 1.0f / (float)NPIX;
        float mean = rs[0] * inv;
        float var  = rq[0] * inv - mean * mean;
        float scl  = rsqrtf(var + 1e-5f) * gamma[c];
        g_scale[c] = scl;
        g_shift[c] = beta[c] - mean * scl;
    }
}

// ---------------- K3: recompute conv -> BN -> relu -> output ----------------
__global__ void __launch_bounds__(128, 4)
k3_output(const float* __restrict__ cw, const float* __restrict__ cb,
          float* __restrict__ out) {
    __shared__ __align__(16) float sw[1728];
    __shared__ __align__(16) float sb[COUT];
    __shared__ float st[6 * 102];
    __shared__ __align__(16) float ssc[COUT];
    __shared__ __align__(16) float ssh[COUT];

    int tx = threadIdx.x, ty = threadIdx.y;
    int tid = ty * 32 + tx;
    load_tile_and_weights(cw, cb, sw, sb, st, tid);
    if (tid < 64) { ssc[tid] = g_scale[tid]; ssh[tid] = g_shift[tid]; }
    __syncthreads();

    u64 acc[32];
    conv_pixel(st, sw, sb, ty, tx, acc);

    // f1: exp/proj/log
    u64 q2 = 0ull;
#pragma unroll
    for (int i = 0; i < 32; ++i) q2 = pfma(acc[i], acc[i], q2);
    float qa, qb; upk(q2, qa, qb);
    u64 f1p = pk2(chain_log_exp(qa + qb));

    // BN affine: u3 = (f1*u)*scale + shift
    u64 n2p = 0ull;
#pragma unroll
    for (int i = 0; i < 32; ++i) {
        u64 sc = *(const u64*)(ssc + 2 * i);
        u64 sh = *(const u64*)(ssh + 2 * i);
        acc[i] = pfma(acc[i], pmul(f1p, sc), sh);
        n2p = pfma(acc[i], acc[i], n2p);
    }
    upk(n2p, qa, qb);
    u64 f2p = pk2(chain_log_exp(qa + qb));   // exp/proj/log again

    // relu in tangent space + norm of relu'd vector
    float nr = 0.0f;
#pragma unroll
    for (int i = 0; i < 32; ++i) {
        u64 w = pmul(acc[i], f2p);
        float a, b; upk(w, a, b);
        a = fmaxf(a, 0.0f); b = fmaxf(b, 0.0f);
        nr = fmaf(a, a, nr); nr = fmaf(b, b, nr);
        acc[i] = pk(a, b);
    }
    u64 f3p = pk2(chain_exp(nr));            // final expmap0 + projx

    int w0 = blockIdx.x * TW, h0 = blockIdx.y * TH, b = blockIdx.z;
    int h = h0 + ty, w = w0 + tx;
    u64* orow = (u64*)(out + ((size_t)(b * H_ + h) * W_ + w) * COUT);
#pragma unroll
    for (int i = 0; i < 32; ++i) orow[i] = pmul(acc[i], f3p);
}

// ---------------- launch -----------------------------------------------------
extern "C" void kernel_launch(void* const* d_in, const int* in_sizes, int n_in,
                              void* d_out, int out_size) {
    const float* x  = (const float*)d_in[0];
    const float* cw = (const float*)d_in[1];
    const float* cb = (const float*)d_in[2];
    const float* gm = (const float*)d_in[3];
    const float* bt = (const float*)d_in[4];
    float* out = (float*)d_out;

    k0_tlog<<<NPIX / 256, 256>>>(x);
    dim3 grid(NBX, NBY, B_), blk(TW, TH);
    k1_stats<<<grid, blk>>>(cw, cb);
    k2_finalize<<<COUT, 256>>>(gm, bt);
    k3_output<<<grid, blk>>>(cw, cb, out);
}

// round 10
// speedup vs baseline: 1.1625x; 1.1625x over previous
#include <cuda_runtime.h>
#include <cstdint>

// ---------------------------------------------------------------------------
// PoincareInputBlock: projx -> logmap0 -> conv3x3+bias -> exp/proj/log ->
// BN(batch stats) -> exp/proj/log -> relu -> expmap0+projx
// x:[16,3,224,224] f32, w:[3,3,3,64] HWIO, out:[16,224,224,64] f32
//
// R7: register-blocked conv. Thread = 4 pixels (rows) x 16 channels (8 f32x2
// pairs). Weights loaded 4xLDS.128 per tap, reused across 4 pixels ->
// ~13x less shared traffic than R6 (which was L1-bound at 81.5%).
// ---------------------------------------------------------------------------

#define B_ 16
#define H_ 224
#define W_ 224
#define CIN 3
#define COUT 64
#define HWSZ (H_*W_)
#define NPIX (B_*H_*W_)          // 802816
#define TW 32
#define TH 4
#define NBX (W_/TW)              // 7
#define NBY (H_/TH)              // 56
#define NBLK (NBX*NBY*B_)        // 6272

typedef unsigned long long u64;

__device__ float g_tlog[NPIX*CIN];          // tangent-space input, NHWC
__device__ float g_partials[128*NBLK];      // per-block sums(64) + sumsq(64)
__device__ float g_scale[COUT];
__device__ float g_shift[COUT];

// ---------------- packed f32x2 helpers -------------------------------------
__device__ __forceinline__ u64 mk64(unsigned lo, unsigned hi) {
    u64 r; asm("mov.b64 %0, {%1, %2};" : "=l"(r) : "r"(lo), "r"(hi)); return r;
}
__device__ __forceinline__ void sp64(u64 v, unsigned& lo, unsigned& hi) {
    asm("mov.b64 {%0, %1}, %2;" : "=r"(lo), "=r"(hi) : "l"(v));
}
__device__ __forceinline__ u64 pk(float a, float b) {
    return mk64(__float_as_uint(a), __float_as_uint(b));
}
__device__ __forceinline__ u64 pk2(float a) { return pk(a, a); }
__device__ __forceinline__ void upk(u64 v, float& a, float& b) {
    unsigned lo, hi; sp64(v, lo, hi);
    a = __uint_as_float(lo); b = __uint_as_float(hi);
}
__device__ __forceinline__ u64 pfma(u64 a, u64 b, u64 c) {
    u64 d;
    asm("fma.rn.f32x2 %0, %1, %2, %3;" : "=l"(d) : "l"(a), "l"(b), "l"(c));
    return d;
}
__device__ __forceinline__ u64 pmul(u64 a, u64 b) {
    u64 d;
    asm("mul.rn.f32x2 %0, %1, %2;" : "=l"(d) : "l"(a), "l"(b));
    return d;
}
__device__ __forceinline__ u64 padd(u64 a, u64 b) {
    u64 d;
    asm("add.rn.f32x2 %0, %1, %2;" : "=l"(d) : "l"(a), "l"(b));
    return d;
}
__device__ __forceinline__ u64 shfl64x(u64 v, int m) {
    unsigned lo, hi; sp64(v, lo, hi);
    lo = __shfl_xor_sync(0xffffffffu, lo, m);
    hi = __shfl_xor_sync(0xffffffffu, hi, m);
    return mk64(lo, hi);
}

// ---------------- robust scalar math (fast-math-proof) ----------------------
__device__ __forceinline__ float my_tanh(float n) {   // n >= 0
    if (n < 0.1f) {
        float n2 = n * n;
        return n * (1.0f + n2 * (-0.33333334f + n2 * 0.13333334f));
    }
    float E = expf(2.0f * n);
    return 1.0f - 2.0f / (E + 1.0f);
}
__device__ __forceinline__ float my_atanh(float t) {  // 0 <= t < 1
    if (t < 0.1f) {
        float t2 = t * t;
        return t * (1.0f + t2 * (0.33333334f + t2 * (0.2f + t2 * 0.14285715f)));
    }
    return 0.5f * logf((1.0f + t) / (1.0f - t));
}
__device__ __forceinline__ float chain_log_exp(float nsq) {
    float nu = sqrtf(nsq);
    float n1 = fmaxf(nu, 1e-7f);
    float th = my_tanh(n1);
    float se = th / n1;
    float hp = se * nu;
    float n2 = fmaxf(hp, 1e-7f);
    float sp = fminf(1.0f, 0.999f / n2);
    float hn = hp * sp;
    float n3 = fmaxf(hn, 1e-7f);
    float tt = fminf(n3, 0.99999f);
    float sl = my_atanh(tt) / n3;
    return sl * sp * se;
}
__device__ __forceinline__ float chain_exp(float nsq) {
    float nu = sqrtf(nsq);
    float n1 = fmaxf(nu, 1e-7f);
    float th = my_tanh(n1);
    float se = th / n1;
    float hp = se * nu;
    float n2 = fmaxf(hp, 1e-7f);
    float sp = fminf(1.0f, 0.999f / n2);
    return se * sp;
}

// ---------------- K0: tangent-space input  (NCHW -> NHWC tlog) --------------
__global__ void k0_tlog(const float* __restrict__ x) {
    int idx = blockIdx.x * 256 + threadIdx.x;
    int b   = idx / HWSZ;
    int hw  = idx - b * HWSZ;
    const float* xb = x + b * (CIN * HWSZ);
    float x0 = xb[hw], x1 = xb[HWSZ + hw], x2 = xb[2 * HWSZ + hw];
    float nsq = x0 * x0 + x1 * x1 + x2 * x2;
    float nu = sqrtf(nsq);
    float n1 = fmaxf(nu, 1e-7f);
    float sp = fminf(1.0f, 0.999f / n1);
    float hn = nu * sp;
    float n3 = fmaxf(hn, 1e-7f);
    float tt = fminf(n3, 0.99999f);
    float g  = sp * my_atanh(tt) / n3;
    float* o = g_tlog + (size_t)idx * 3;
    o[0] = g * x0; o[1] = g * x1; o[2] = g * x2;
}

// ---------------- shared staging -------------------------------------------
// sw2: weights padded per tap/cg: [27 taps][4 cg][20 floats (16 used)]
// st : input tile [6 rows][34 cols][3 ci]
__device__ __forceinline__ void stage_common(
        const float* __restrict__ cw, float* sw2, float* st, int tid) {
    for (int i = tid; i < 1728; i += 128) {
        int tap = i >> 6, r = i & 63;
        sw2[tap * 80 + (r >> 4) * 20 + (r & 15)] = cw[i];
    }
    int x0 = blockIdx.x * TW, y0 = blockIdx.y * TH, b = blockIdx.z;
    for (int i = tid; i < 612; i += 128) {
        int r  = i / 102;
        int k  = i - r * 102;
        int c  = k / 3;
        int ci = k - 3 * c;
        int gh = y0 - 1 + r;
        int gw = x0 - 1 + c;
        float v = 0.0f;
        if ((unsigned)gh < (unsigned)H_ && (unsigned)gw < (unsigned)W_)
            v = g_tlog[((size_t)(b * H_ + gh) * W_ + gw) * 3 + ci];
        st[i] = v;
    }
}

// conv core: acc[p][i] = conv+bias for pixel row y0+p, pairs cg*8+i
__device__ __forceinline__ void conv4x8(const float* st, const float* sw2,
                                        const float* sbp, int cg, int xw,
                                        u64 acc[4][8]) {
    {
        const uint4* bp = (const uint4*)(sbp + cg * 20);
        uint4 b0 = bp[0], b1 = bp[1], b2 = bp[2], b3 = bp[3];
        u64 bb[8] = { mk64(b0.x, b0.y), mk64(b0.z, b0.w),
                      mk64(b1.x, b1.y), mk64(b1.z, b1.w),
                      mk64(b2.x, b2.y), mk64(b2.z, b2.w),
                      mk64(b3.x, b3.y), mk64(b3.z, b3.w) };
#pragma unroll
        for (int p = 0; p < 4; ++p)
#pragma unroll
            for (int i = 0; i < 8; ++i) acc[p][i] = bb[i];
    }
#pragma unroll
    for (int dx = 0; dx < 3; ++dx)
#pragma unroll
        for (int ci = 0; ci < 3; ++ci) {
            float tv[6];
#pragma unroll
            for (int r = 0; r < 6; ++r)
                tv[r] = st[(r * 34 + xw + dx) * 3 + ci];
#pragma unroll
            for (int dy = 0; dy < 3; ++dy) {
                const uint4* wp = (const uint4*)(sw2 + ((dy * 3 + dx) * 3 + ci) * 80 + cg * 20);
                uint4 a0 = wp[0], a1 = wp[1], a2 = wp[2], a3 = wp[3];
                u64 w8[8] = { mk64(a0.x, a0.y), mk64(a0.z, a0.w),
                              mk64(a1.x, a1.y), mk64(a1.z, a1.w),
                              mk64(a2.x, a2.y), mk64(a2.z, a2.w),
                              mk64(a3.x, a3.y), mk64(a3.z, a3.w) };
#pragma unroll
                for (int p = 0; p < 4; ++p) {
                    u64 tv2 = pk2(tv[p + dy]);
#pragma unroll
                    for (int i = 0; i < 8; ++i)
                        acc[p][i] = pfma(tv2, w8[i], acc[p][i]);
                }
            }
        }
}

// ---------------- K1: conv + f1 -> per-block channel stats ------------------
__global__ void __launch_bounds__(128, 3)
k1_stats(const float* __restrict__ cw, const float* __restrict__ cb) {
    __shared__ __align__(16) float sw2[27 * 80];
    __shared__ __align__(16) float sb2[4 * 20];
    __shared__ float st[612];
    __shared__ u64 wsum[4][32], wqsum[4][32];

    int tid = threadIdx.x;
    int lane = tid & 31, w = tid >> 5;
    int cg = lane >> 3, xo = lane & 7;
    int xw = w * 8 + xo;

    stage_common(cw, sw2, st, tid);
    if (tid < 64) sb2[(tid >> 4) * 20 + (tid & 15)] = cb[tid];
    __syncthreads();

    u64 acc[4][8];
    conv4x8(st, sw2, sb2, cg, xw, acc);

    // per-pixel squared norm (partial over 16 ch) + butterfly over cg bits
    float f1[4];
#pragma unroll
    for (int p = 0; p < 4; ++p) {
        u64 q2 = 0ull;
#pragma unroll
        for (int i = 0; i < 8; ++i) q2 = pfma(acc[p][i], acc[p][i], q2);
        float a, b; upk(q2, a, b);
        float ns = a + b;
        ns += __shfl_xor_sync(0xffffffffu, ns, 8);
        ns += __shfl_xor_sync(0xffffffffu, ns, 16);
        f1[p] = chain_log_exp(ns);
    }

    // u2 = f1*u; accumulate per-pair sum/sumsq over the 4 pixels
    u64 s[8], q[8];
#pragma unroll
    for (int i = 0; i < 8; ++i) { s[i] = 0ull; q[i] = 0ull; }
#pragma unroll
    for (int p = 0; p < 4; ++p) {
        u64 f1p = pk2(f1[p]);
#pragma unroll
        for (int i = 0; i < 8; ++i) {
            u64 v = pmul(acc[p][i], f1p);
            s[i] = padd(s[i], v);
            q[i] = pfma(v, v, q[i]);
        }
    }
    // butterfly over xo bits (8 lanes share same cg)
#pragma unroll
    for (int m = 1; m <= 4; m <<= 1)
#pragma unroll
        for (int i = 0; i < 8; ++i) {
            s[i] = padd(s[i], shfl64x(s[i], m));
            q[i] = padd(q[i], shfl64x(q[i], m));
        }
    if (xo == 0)
#pragma unroll
        for (int i = 0; i < 8; ++i) {
            wsum[w][cg * 8 + i]  = s[i];
            wqsum[w][cg * 8 + i] = q[i];
        }
    __syncthreads();
    if (tid < 32) {
        u64 S = padd(padd(wsum[0][tid],  wsum[1][tid]),
                     padd(wsum[2][tid],  wsum[3][tid]));
        u64 Q = padd(padd(wqsum[0][tid], wqsum[1][tid]),
                     padd(wqsum[2][tid], wqsum[3][tid]));
        float s0, s1, q0, q1;
        upk(S, s0, s1); upk(Q, q0, q1);
        int blk = (blockIdx.z * NBY + blockIdx.y) * NBX + blockIdx.x;
        g_partials[(2 * tid) * NBLK + blk]          = s0;
        g_partials[(2 * tid + 1) * NBLK + blk]      = s1;
        g_partials[(64 + 2 * tid) * NBLK + blk]     = q0;
        g_partials[(64 + 2 * tid + 1) * NBLK + blk] = q1;
    }
}

// ---------------- K2: finalize BN scale/shift (deterministic) ---------------
__global__ void k2_finalize(const float* __restrict__ gamma,
                            const float* __restrict__ beta) {
    int c = blockIdx.x, tid = threadIdx.x;
    const float* ps = g_partials + (size_t)c * NBLK;
    const float* pq = g_partials + (size_t)(64 + c) * NBLK;
    float s = 0.0f, q = 0.0f;
    for (int i = tid; i < NBLK; i += 256) { s += ps[i]; q += pq[i]; }
    __shared__ float rs[256], rq[256];
    rs[tid] = s; rq[tid] = q;
    __syncthreads();
    for (int stp = 128; stp > 0; stp >>= 1) {
        if (tid < stp) { rs[tid] += rs[tid + stp]; rq[tid] += rq[tid + stp]; }
        __syncthreads();
    }
    if (tid == 0) {
        float inv  = 1.0f / (float)NPIX;
        float mean = rs[0] * inv;
        float var  = rq[0] * inv - mean * mean;
        float scl  = rsqrtf(var + 1e-5f) * gamma[c];
        g_scale[c] = scl;
        g_shift[c] = beta[c] - mean * scl;
    }
}

// ---------------- K3: recompute conv -> BN -> relu -> output ----------------
__global__ void __launch_bounds__(128, 3)
k3_output(const float* __restrict__ cw, const float* __restrict__ cb,
          float* __restrict__ out) {
    __shared__ __align__(16) float sw2[27 * 80];
    __shared__ __align__(16) float sb2[4 * 20];
    __shared__ __align__(16) float ssc[4 * 20];
    __shared__ __align__(16) float ssh[4 * 20];
    __shared__ float st[612];

    int tid = threadIdx.x;
    int lane = tid & 31, w = tid >> 5;
    int cg = lane >> 3, xo = lane & 7;
    int xw = w * 8 + xo;

    stage_common(cw, sw2, st, tid);
    if (tid < 64) {
        int d = (tid >> 4) * 20 + (tid & 15);
        sb2[d] = cb[tid];
        ssc[d] = g_scale[tid];
        ssh[d] = g_shift[tid];
    }
    __syncthreads();

    u64 acc[4][8];
    conv4x8(st, sw2, sb2, cg, xw, acc);

    // f1 per pixel
    float f1[4];
#pragma unroll
    for (int p = 0; p < 4; ++p) {
        u64 q2 = 0ull;
#pragma unroll
        for (int i = 0; i < 8; ++i) q2 = pfma(acc[p][i], acc[p][i], q2);
        float a, b; upk(q2, a, b);
        float ns = a + b;
        ns += __shfl_xor_sync(0xffffffffu, ns, 8);
        ns += __shfl_xor_sync(0xffffffffu, ns, 16);
        f1[p] = chain_log_exp(ns);
    }

    // BN affine pairs for this cg
    u64 scp[8], shp[8];
    {
        const uint4* cp = (const uint4*)(ssc + cg * 20);
        const uint4* hp = (const uint4*)(ssh + cg * 20);
        uint4 c0 = cp[0], c1 = cp[1], c2 = cp[2], c3 = cp[3];
        uint4 h0 = hp[0], h1 = hp[1], h2 = hp[2], h3 = hp[3];
        scp[0] = mk64(c0.x, c0.y); scp[1] = mk64(c0.z, c0.w);
        scp[2] = mk64(c1.x, c1.y); scp[3] = mk64(c1.z, c1.w);
        scp[4] = mk64(c2.x, c2.y); scp[5] = mk64(c2.z, c2.w);
        scp[6] = mk64(c3.x, c3.y); scp[7] = mk64(c3.z, c3.w);
        shp[0] = mk64(h0.x, h0.y); shp[1] = mk64(h0.z, h0.w);
        shp[2] = mk64(h1.x, h1.y); shp[3] = mk64(h1.z, h1.w);
        shp[4] = mk64(h2.x, h2.y); shp[5] = mk64(h2.z, h2.w);
        shp[6] = mk64(h3.x, h3.y); shp[7] = mk64(h3.z, h3.w);
    }

    int x0 = blockIdx.x * TW, y0 = blockIdx.y * TH, b = blockIdx.z;

#pragma unroll
    for (int p = 0; p < 4; ++p) {
        u64 f1p = pk2(f1[p]);
        // u3 = (f1*u)*scale + shift
        u64 u3[8];
        u64 n2 = 0ull;
#pragma unroll
        for (int i = 0; i < 8; ++i) {
            u3[i] = pfma(acc[p][i], pmul(f1p, scp[i]), shp[i]);
            n2 = pfma(u3[i], u3[i], n2);
        }
        float a, bb; upk(n2, a, bb);
        float ns2 = a + bb;
        ns2 += __shfl_xor_sync(0xffffffffu, ns2, 8);
        ns2 += __shfl_xor_sync(0xffffffffu, ns2, 16);
        u64 f2p = pk2(chain_log_exp(ns2));

        // relu in tangent space + norm
        float nr = 0.0f;
#pragma unroll
        for (int i = 0; i < 8; ++i) {
            u64 v = pmul(u3[i], f2p);
            float va, vb; upk(v, va, vb);
            va = fmaxf(va, 0.0f); vb = fmaxf(vb, 0.0f);
            nr = fmaf(va, va, nr); nr = fmaf(vb, vb, nr);
            u3[i] = pk(va, vb);
        }
        nr += __shfl_xor_sync(0xffffffffu, nr, 8);
        nr += __shfl_xor_sync(0xffffffffu, nr, 16);
        u64 f3p = pk2(chain_exp(nr));

        // store: 4x STG.128 per pixel, coalesced within warp
        float* po = out + ((size_t)(b * H_ + y0 + p) * W_ + x0 + xw) * COUT + cg * 16;
        union { u64 d[2]; uint4 v; } o0, o1, o2, o3;
        o0.d[0] = pmul(u3[0], f3p); o0.d[1] = pmul(u3[1], f3p);
        o1.d[0] = pmul(u3[2], f3p); o1.d[1] = pmul(u3[3], f3p);
        o2.d[0] = pmul(u3[4], f3p); o2.d[1] = pmul(u3[5], f3p);
        o3.d[0] = pmul(u3[6], f3p); o3.d[1] = pmul(u3[7], f3p);
        uint4* pv = (uint4*)po;
        pv[0] = o0.v; pv[1] = o1.v; pv[2] = o2.v; pv[3] = o3.v;
    }
}

// ---------------- launch -----------------------------------------------------
extern "C" void kernel_launch(void* const* d_in, const int* in_sizes, int n_in,
                              void* d_out, int out_size) {
    const float* x  = (const float*)d_in[0];
    const float* cw = (const float*)d_in[1];
    const float* cb = (const float*)d_in[2];
    const float* gm = (const float*)d_in[3];
    const float* bt = (const float*)d_in[4];
    float* out = (float*)d_out;

    k0_tlog<<<NPIX / 256, 256>>>(x);
    dim3 grid(NBX, NBY, B_), blk(128);
    k1_stats<<<grid, blk>>>(cw, cb);
    k2_finalize<<<COUT, 256>>>(gm, bt);
    k3_output<<<grid, blk>>>(cw, cb, out);
}

// round 14
// speedup vs baseline: 1.4250x; 1.2258x over previous
#include <cuda_runtime.h>
#include <cstdint>

// ---------------------------------------------------------------------------
// PoincareInputBlock: projx -> logmap0 -> conv3x3+bias -> exp/proj/log ->
// BN(batch stats) -> exp/proj/log -> relu -> expmap0+projx
// x:[16,3,224,224] f32, w:[3,3,3,64] HWIO, out:[16,224,224,64] f32
//
// R11: latency-focused epilogue. 4-pixel ILP through the transcendental
// chains, branchless MUFU-based tanh/atanh, srel trick to break the
// f2->relu->f3 serial dependency, ulonglong2 smem loads (no pack movs),
// launch_bounds(128,4) for 25% occupancy.
// ---------------------------------------------------------------------------

#define B_ 16
#define H_ 224
#define W_ 224
#define CIN 3
#define COUT 64
#define HWSZ (H_*W_)
#define NPIX (B_*H_*W_)          // 802816
#define TW 32
#define TH 4
#define NBX (W_/TW)              // 7
#define NBY (H_/TH)              // 56
#define NBLK (NBX*NBY*B_)        // 6272

typedef unsigned long long u64;

__device__ float g_tlog[NPIX*CIN];          // tangent-space input, NHWC
__device__ float g_partials[128*NBLK];      // per-block sums(64) + sumsq(64)
__device__ float g_scale[COUT];
__device__ float g_shift[COUT];

// ---------------- packed f32x2 helpers -------------------------------------
__device__ __forceinline__ u64 mk64(unsigned lo, unsigned hi) {
    u64 r; asm("mov.b64 %0, {%1, %2};" : "=l"(r) : "r"(lo), "r"(hi)); return r;
}
__device__ __forceinline__ void sp64(u64 v, unsigned& lo, unsigned& hi) {
    asm("mov.b64 {%0, %1}, %2;" : "=r"(lo), "=r"(hi) : "l"(v));
}
__device__ __forceinline__ u64 pk(float a, float b) {
    return mk64(__float_as_uint(a), __float_as_uint(b));
}
__device__ __forceinline__ u64 pk2(float a) { return pk(a, a); }
__device__ __forceinline__ void upk(u64 v, float& a, float& b) {
    unsigned lo, hi; sp64(v, lo, hi);
    a = __uint_as_float(lo); b = __uint_as_float(hi);
}
__device__ __forceinline__ u64 pfma(u64 a, u64 b, u64 c) {
    u64 d;
    asm("fma.rn.f32x2 %0, %1, %2, %3;" : "=l"(d) : "l"(a), "l"(b), "l"(c));
    return d;
}
__device__ __forceinline__ u64 pmul(u64 a, u64 b) {
    u64 d;
    asm("mul.rn.f32x2 %0, %1, %2;" : "=l"(d) : "l"(a), "l"(b));
    return d;
}
__device__ __forceinline__ u64 padd(u64 a, u64 b) {
    u64 d;
    asm("add.rn.f32x2 %0, %1, %2;" : "=l"(d) : "l"(a), "l"(b));
    return d;
}
__device__ __forceinline__ u64 shfl64x(u64 v, int m) {
    unsigned lo, hi; sp64(v, lo, hi);
    lo = __shfl_xor_sync(0xffffffffu, lo, m);
    hi = __shfl_xor_sync(0xffffffffu, hi, m);
    return mk64(lo, hi);
}
// 8 pairs = 4x LDS.128 straight into u64 regs (no pack movs)
__device__ __forceinline__ void ld8(const float* base, u64 w8[8]) {
    const ulonglong2* p = (const ulonglong2*)base;
    ulonglong2 a = p[0], b = p[1], c = p[2], d = p[3];
    w8[0] = a.x; w8[1] = a.y; w8[2] = b.x; w8[3] = b.y;
    w8[4] = c.x; w8[5] = c.y; w8[6] = d.x; w8[7] = d.y;
}

// ---------------- fast branchless Poincare chains ---------------------------
// scale of logmap0(projx(expmap0(v))) given ||v||^2
__device__ __forceinline__ float fchain_log_exp(float nsq) {
    float nu = sqrtf(nsq);
    float n1 = fmaxf(nu, 1e-7f);
    float E  = __expf(2.0f * n1);
    float th = 1.0f - __fdividef(2.0f, E + 1.0f);   // tanh(n1)
    float hp = fminf(th, nu);                       // = (th/n1)*nu exactly
    float sp = fminf(1.0f, __fdividef(0.999f, fmaxf(hp, 1e-7f)));
    float n3 = fmaxf(hp * sp, 1e-7f);
    float tt = fminf(n3, 0.99999f);
    float L  = 0.5f * __logf(__fdividef(1.0f + tt, 1.0f - tt));  // atanh(tt)
    return __fdividef(L * sp * th, n3 * n1);        // sl*sp*se
}
// scale of projx(expmap0(v)) given ||v||^2
__device__ __forceinline__ float fchain_exp(float nsq) {
    float nu = sqrtf(nsq);
    float n1 = fmaxf(nu, 1e-7f);
    float E  = __expf(2.0f * n1);
    float th = 1.0f - __fdividef(2.0f, E + 1.0f);
    float hp = fminf(th, nu);
    float sp = fminf(1.0f, __fdividef(0.999f, fmaxf(hp, 1e-7f)));
    return __fdividef(th, n1) * sp;
}

// ---------------- robust scalar math (k0 only; runs once, tiny) -------------
__device__ __forceinline__ float my_atanh(float t) {  // 0 <= t < 1
    if (t < 0.1f) {
        float t2 = t * t;
        return t * (1.0f + t2 * (0.33333334f + t2 * (0.2f + t2 * 0.14285715f)));
    }
    return 0.5f * logf((1.0f + t) / (1.0f - t));
}

// ---------------- K0: tangent-space input  (NCHW -> NHWC tlog) --------------
__global__ void k0_tlog(const float* __restrict__ x) {
    int idx = blockIdx.x * 256 + threadIdx.x;
    int b   = idx / HWSZ;
    int hw  = idx - b * HWSZ;
    const float* xb = x + b * (CIN * HWSZ);
    float x0 = xb[hw], x1 = xb[HWSZ + hw], x2 = xb[2 * HWSZ + hw];
    float nsq = x0 * x0 + x1 * x1 + x2 * x2;
    float nu = sqrtf(nsq);
    float n1 = fmaxf(nu, 1e-7f);
    float sp = fminf(1.0f, 0.999f / n1);
    float hn = nu * sp;
    float n3 = fmaxf(hn, 1e-7f);
    float tt = fminf(n3, 0.99999f);
    float g  = sp * my_atanh(tt) / n3;
    float* o = g_tlog + (size_t)idx * 3;
    o[0] = g * x0; o[1] = g * x1; o[2] = g * x2;
}

// ---------------- shared staging -------------------------------------------
// sw2: weights padded per tap/cg: [27 taps][4 cg][20 floats (16 used)]
// st : input tile [6 rows][34 cols][3 ci]
__device__ __forceinline__ void stage_common(
        const float* __restrict__ cw, float* sw2, float* st, int tid) {
    for (int i = tid; i < 1728; i += 128) {
        int tap = i >> 6, r = i & 63;
        sw2[tap * 80 + (r >> 4) * 20 + (r & 15)] = cw[i];
    }
    int x0 = blockIdx.x * TW, y0 = blockIdx.y * TH, b = blockIdx.z;
    for (int i = tid; i < 612; i += 128) {
        int r  = i / 102;
        int k  = i - r * 102;
        int c  = k / 3;
        int ci = k - 3 * c;
        int gh = y0 - 1 + r;
        int gw = x0 - 1 + c;
        float v = 0.0f;
        if ((unsigned)gh < (unsigned)H_ && (unsigned)gw < (unsigned)W_)
            v = g_tlog[((size_t)(b * H_ + gh) * W_ + gw) * 3 + ci];
        st[i] = v;
    }
}

// conv core: acc[p][i] = conv+bias for pixel row y0+p, pairs cg*8+i
__device__ __forceinline__ void conv4x8(const float* st, const float* sw2,
                                        const float* sbp, int cg, int xw,
                                        u64 acc[4][8]) {
    {
        u64 bb[8];
        ld8(sbp + cg * 20, bb);
#pragma unroll
        for (int p = 0; p < 4; ++p)
#pragma unroll
            for (int i = 0; i < 8; ++i) acc[p][i] = bb[i];
    }
#pragma unroll
    for (int dx = 0; dx < 3; ++dx)
#pragma unroll
        for (int ci = 0; ci < 3; ++ci) {
            u64 tv2[6];
#pragma unroll
            for (int r = 0; r < 6; ++r)
                tv2[r] = pk2(st[(r * 34 + xw + dx) * 3 + ci]);
#pragma unroll
            for (int dy = 0; dy < 3; ++dy) {
                u64 w8[8];
                ld8(sw2 + ((dy * 3 + dx) * 3 + ci) * 80 + cg * 20, w8);
#pragma unroll
                for (int p = 0; p < 4; ++p)
#pragma unroll
                    for (int i = 0; i < 8; ++i)
                        acc[p][i] = pfma(tv2[p + dy], w8[i], acc[p][i]);
            }
        }
}

// ---------------- K1: conv + f1 -> per-block channel stats ------------------
__global__ void __launch_bounds__(128, 4)
k1_stats(const float* __restrict__ cw, const float* __restrict__ cb) {
    __shared__ __align__(16) float sw2[27 * 80];
    __shared__ __align__(16) float sb2[4 * 20];
    __shared__ float st[612];
    __shared__ u64 wsum[4][32], wqsum[4][32];

    int tid = threadIdx.x;
    int lane = tid & 31, w = tid >> 5;
    int cg = lane >> 3, xo = lane & 7;
    int xw = w * 8 + xo;

    stage_common(cw, sw2, st, tid);
    if (tid < 64) sb2[(tid >> 4) * 20 + (tid & 15)] = cb[tid];
    __syncthreads();

    u64 acc[4][8];
    conv4x8(st, sw2, sb2, cg, xw, acc);

    // stage 1: all 4 squared norms (shfl over cg bits), then 4 chains (ILP)
    float ns[4];
#pragma unroll
    for (int p = 0; p < 4; ++p) {
        u64 q2 = 0ull;
#pragma unroll
        for (int i = 0; i < 8; ++i) q2 = pfma(acc[p][i], acc[p][i], q2);
        float a, b; upk(q2, a, b);
        float v = a + b;
        v += __shfl_xor_sync(0xffffffffu, v, 8);
        v += __shfl_xor_sync(0xffffffffu, v, 16);
        ns[p] = v;
    }
    float f1v[4];
#pragma unroll
    for (int p = 0; p < 4; ++p) f1v[p] = fchain_log_exp(ns[p]);

    // u2 = f1*u; accumulate per-pair sum/sumsq over the 4 pixels
    u64 s[8], q[8];
#pragma unroll
    for (int i = 0; i < 8; ++i) { s[i] = 0ull; q[i] = 0ull; }
#pragma unroll
    for (int p = 0; p < 4; ++p) {
        u64 f1p = pk2(f1v[p]);
#pragma unroll
        for (int i = 0; i < 8; ++i) {
            u64 v = pmul(acc[p][i], f1p);
            s[i] = padd(s[i], v);
            q[i] = pfma(v, v, q[i]);
        }
    }
    // butterfly over xo bits (8 lanes share same cg)
#pragma unroll
    for (int m = 1; m <= 4; m <<= 1)
#pragma unroll
        for (int i = 0; i < 8; ++i) {
            s[i] = padd(s[i], shfl64x(s[i], m));
            q[i] = padd(q[i], shfl64x(q[i], m));
        }
    if (xo == 0)
#pragma unroll
        for (int i = 0; i < 8; ++i) {
            wsum[w][cg * 8 + i]  = s[i];
            wqsum[w][cg * 8 + i] = q[i];
        }
    __syncthreads();
    if (tid < 32) {
        u64 S = padd(padd(wsum[0][tid],  wsum[1][tid]),
                     padd(wsum[2][tid],  wsum[3][tid]));
        u64 Q = padd(padd(wqsum[0][tid], wqsum[1][tid]),
                     padd(wqsum[2][tid], wqsum[3][tid]));
        float s0, s1, q0, q1;
        upk(S, s0, s1); upk(Q, q0, q1);
        int blk = (blockIdx.z * NBY + blockIdx.y) * NBX + blockIdx.x;
        g_partials[(2 * tid) * NBLK + blk]          = s0;
        g_partials[(2 * tid + 1) * NBLK + blk]      = s1;
        g_partials[(64 + 2 * tid) * NBLK + blk]     = q0;
        g_partials[(64 + 2 * tid + 1) * NBLK + blk] = q1;
    }
}

// ---------------- K2: finalize BN scale/shift (deterministic) ---------------
__global__ void k2_finalize(const float* __restrict__ gamma,
                            const float* __restrict__ beta) {
    int c = blockIdx.x, tid = threadIdx.x;
    const float* ps = g_partials + (size_t)c * NBLK;
    const float* pq = g_partials + (size_t)(64 + c) * NBLK;
    float s = 0.0f, q = 0.0f;
    for (int i = tid; i < NBLK; i += 256) { s += ps[i]; q += pq[i]; }
    __shared__ float rs[256], rq[256];
    rs[tid] = s; rq[tid] = q;
    __syncthreads();
    for (int stp = 128; stp > 0; stp >>= 1) {
        if (tid < stp) { rs[tid] += rs[tid + stp]; rq[tid] += rq[tid + stp]; }
        __syncthreads();
    }
    if (tid == 0) {
        float inv  = 1.0f / (float)NPIX;
        float mean = rs[0] * inv;
        float var  = rq[0] * inv - mean * mean;
        float scl  = rsqrtf(var + 1e-5f) * gamma[c];
        g_scale[c] = scl;
        g_shift[c] = beta[c] - mean * scl;
    }
}

// ---------------- K3: recompute conv -> BN -> relu -> output ----------------
__global__ void __launch_bounds__(128, 4)
k3_output(const float* __restrict__ cw, const float* __restrict__ cb,
          float* __restrict__ out) {
    __shared__ __align__(16) float sw2[27 * 80];
    __shared__ __align__(16) float sb2[4 * 20];
    __shared__ __align__(16) float ssc[4 * 20];
    __shared__ __align__(16) float ssh[4 * 20];
    __shared__ float st[612];

    int tid = threadIdx.x;
    int lane = tid & 31, w = tid >> 5;
    int cg = lane >> 3, xo = lane & 7;
    int xw = w * 8 + xo;

    stage_common(cw, sw2, st, tid);
    if (tid < 64) {
        int d = (tid >> 4) * 20 + (tid & 15);
        sb2[d] = cb[tid];
        ssc[d] = g_scale[tid];
        ssh[d] = g_shift[tid];
    }
    __syncthreads();

    u64 acc[4][8];
    conv4x8(st, sw2, sb2, cg, xw, acc);

    // stage 1: all 4 norms, then 4 f1 chains with ILP
    float ns[4];
#pragma unroll
    for (int p = 0; p < 4; ++p) {
        u64 q2 = 0ull;
#pragma unroll
        for (int i = 0; i < 8; ++i) q2 = pfma(acc[p][i], acc[p][i], q2);
        float a, b; upk(q2, a, b);
        float v = a + b;
        v += __shfl_xor_sync(0xffffffffu, v, 8);
        v += __shfl_xor_sync(0xffffffffu, v, 16);
        ns[p] = v;
    }
    float f1v[4];
#pragma unroll
    for (int p = 0; p < 4; ++p) f1v[p] = fchain_log_exp(ns[p]);

    // stage 2: u3 = (f1*u)*scale + shift; ns2 = ||u3||^2;
    //          srel = ||relu(u3)||^2 (relu mask is f2-invariant);
    //          acc <- relu(u3)
    u64 scp[8], shp[8];
    ld8(ssc + cg * 20, scp);
    ld8(ssh + cg * 20, shp);
    float ns2[4], srel[4];
#pragma unroll
    for (int p = 0; p < 4; ++p) {
        u64 f1p = pk2(f1v[p]);
        u64 n2 = 0ull;
        float sr = 0.0f;
#pragma unroll
        for (int i = 0; i < 8; ++i) {
            u64 u3 = pfma(acc[p][i], pmul(f1p, scp[i]), shp[i]);
            n2 = pfma(u3, u3, n2);
            float a, b; upk(u3, a, b);
            a = fmaxf(a, 0.0f); b = fmaxf(b, 0.0f);
            sr = fmaf(a, a, sr); sr = fmaf(b, b, sr);
            acc[p][i] = pk(a, b);
        }
        float a, b; upk(n2, a, b);
        float v = a + b;
        v  += __shfl_xor_sync(0xffffffffu, v, 8);
        v  += __shfl_xor_sync(0xffffffffu, v, 16);
        sr += __shfl_xor_sync(0xffffffffu, sr, 8);
        sr += __shfl_xor_sync(0xffffffffu, sr, 16);
        ns2[p] = v; srel[p] = sr;
    }

    // stage 3: f2 chains (ILP x4), then f3 chains (ILP x4), fused scale
    float f2v[4];
#pragma unroll
    for (int p = 0; p < 4; ++p) f2v[p] = fchain_log_exp(ns2[p]);
    float sf[4];
#pragma unroll
    for (int p = 0; p < 4; ++p) {
        float f3 = fchain_exp(f2v[p] * f2v[p] * srel[p]);
        sf[p] = f2v[p] * f3;
    }

    // stage 4: scaled stores, 4x STG.128 per pixel, coalesced
    int x0 = blockIdx.x * TW, y0 = blockIdx.y * TH, b = blockIdx.z;
#pragma unroll
    for (int p = 0; p < 4; ++p) {
        u64 sfp = pk2(sf[p]);
        float* po = out + ((size_t)(b * H_ + y0 + p) * W_ + x0 + xw) * COUT + cg * 16;
        ulonglong2* pv = (ulonglong2*)po;
        ulonglong2 v0, v1, v2, v3;
        v0.x = pmul(acc[p][0], sfp); v0.y = pmul(acc[p][1], sfp);
        v1.x = pmul(acc[p][2], sfp); v1.y = pmul(acc[p][3], sfp);
        v2.x = pmul(acc[p][4], sfp); v2.y = pmul(acc[p][5], sfp);
        v3.x = pmul(acc[p][6], sfp); v3.y = pmul(acc[p][7], sfp);
        pv[0] = v0; pv[1] = v1; pv[2] = v2; pv[3] = v3;
    }
}

// ---------------- launch -----------------------------------------------------
extern "C" void kernel_launch(void* const* d_in, const int* in_sizes, int n_in,
                              void* d_out, int out_size) {
    const float* x  = (const float*)d_in[0];
    const float* cw = (const float*)d_in[1];
    const float* cb = (const float*)d_in[2];
    const float* gm = (const float*)d_in[3];
    const float* bt = (const float*)d_in[4];
    float* out = (float*)d_out;

    k0_tlog<<<NPIX / 256, 256>>>(x);
    dim3 grid(NBX, NBY, B_), blk(128);
    k1_stats<<<grid, blk>>>(cw, cb);
    k2_finalize<<<COUT, 256>>>(gm, bt);
    k3_output<<<grid, blk>>>(cw, cb, out);
}